// round 7
// baseline (speedup 1.0000x reference)
#include <cuda_runtime.h>
#include <cuda_fp16.h>
#include <cstdint>

// ============================================================
// out[8192,4096] = x[8192,4096] @ sign(W)[4096,4096]^T + sign(b)
// Base-PTX tensor path: cp.async + ldmatrix + mma.sync.m16n8k16.f32.f16.
// R7: mbarrier full/empty rings replace cp.async.wait_group+__syncthreads.
//     Only convergence point is the empty-wait at ~1-iteration distance,
//     so warps decouple instead of re-converging every k-tile.
// ============================================================

static constexpr int M = 8192;
static constexpr int N = 4096;
static constexpr int K = 4096;

static constexpr int BM = 128;
static constexpr int BN = 128;
static constexpr int BK = 64;
static constexpr int KT = K / BK;          // 64 k-tiles
static constexpr int STAGES = 3;

static constexpr int ROW_HALFS = BK + 8;   // 72 halves = 144B row (9x16B, conflict-free)
static constexpr int ROW_BYTES = ROW_HALFS * 2;              // 144
static constexpr int TILE_BYTES = BM * ROW_BYTES;            // 18432
static constexpr int STAGE_BYTES = 2 * TILE_BYTES;           // 36864 (A then B)
static constexpr int SMEM_DATA = 1024;                       // barriers below
static constexpr int SMEM_TOTAL = SMEM_DATA + STAGES * STAGE_BYTES; // 111616

// ---------------- scratch (__device__ globals: alloc-free rule) ------------
__device__ __half g_xh[(size_t)M * K];   // fp16(x)
__device__ __half g_wh[(size_t)N * K];   // fp16(sign(W))
__device__ float  g_bs[N];               // sign(bias)

// ---------------- PTX helpers -----------------------------------------------
__device__ __forceinline__ uint32_t smem_u32(const void* p) {
    uint32_t a;
    asm("{ .reg .u64 t; cvta.to.shared.u64 t, %1; cvt.u32.u64 %0, t; }"
        : "=r"(a) : "l"(p));
    return a;
}

__device__ __forceinline__ void cp16(uint32_t s, const void* g) {
    asm volatile("cp.async.cg.shared.global [%0], [%1], 16;"
                 :: "r"(s), "l"(g) : "memory");
}

#define MBAR_INIT(a, c) \
    asm volatile("mbarrier.init.shared.b64 [%0], %1;" :: "r"(a), "r"((uint32_t)(c)) : "memory")
#define MBAR_ARRIVE(a) \
    asm volatile("mbarrier.arrive.shared.b64 _, [%0];" :: "r"(a) : "memory")
// arrive on mbarrier when all of this thread's prior cp.asyncs complete
#define CP_MBAR_ARRIVE(a) \
    asm volatile("cp.async.mbarrier.arrive.noinc.shared.b64 [%0];" :: "r"(a) : "memory")

#define MBAR_WAIT(a, ph) do {                                               \
    uint32_t _m = (a); uint32_t _p = (ph); uint32_t _d;                     \
    asm volatile("{ .reg .pred p;"                                          \
        " mbarrier.try_wait.parity.shared.b64 p, [%1], %2;"                 \
        " selp.b32 %0, 1, 0, p; }" : "=r"(_d) : "r"(_m), "r"(_p) : "memory");\
    if (!_d) {                                                              \
        asm volatile("{ .reg .pred P1;"                                     \
            " WL_%=: mbarrier.try_wait.parity.shared.b64 P1, [%0], %1, 0x989680;"\
            " @P1 bra.uni WD_%=; bra.uni WL_%=; WD_%=: }"                   \
            :: "r"(_m), "r"(_p) : "memory");                                \
    } } while (0)

__device__ __forceinline__ void ldsm4(uint32_t* r, uint32_t addr) {
    asm volatile("ldmatrix.sync.aligned.m8n8.x4.shared.b16 {%0,%1,%2,%3}, [%4];"
                 : "=r"(r[0]), "=r"(r[1]), "=r"(r[2]), "=r"(r[3]) : "r"(addr));
}

__device__ __forceinline__ void mma16816(float* c, const uint32_t* a,
                                         uint32_t b0, uint32_t b1) {
    asm volatile(
        "mma.sync.aligned.m16n8k16.row.col.f32.f16.f16.f32 "
        "{%0,%1,%2,%3}, {%4,%5,%6,%7}, {%8,%9}, {%0,%1,%2,%3};"
        : "+f"(c[0]), "+f"(c[1]), "+f"(c[2]), "+f"(c[3])
        : "r"(a[0]), "r"(a[1]), "r"(a[2]), "r"(a[3]), "r"(b0), "r"(b1));
}

// ---------------- prep: fp32 -> fp16 / sign ---------------------------------
__device__ __forceinline__ float fsign(float v) {
    return (v > 0.f) ? 1.f : ((v < 0.f) ? -1.f : 0.f);
}

__global__ void prep_kernel(const float* __restrict__ x,
                            const float* __restrict__ w,
                            const float* __restrict__ b) {
    const long tid = (long)blockIdx.x * blockDim.x + threadIdx.x;
    const long stride = (long)gridDim.x * blockDim.x;
    const long NX4 = ((long)M * K) / 4;
    const long NW4 = ((long)N * K) / 4;

    __half2* xh2 = reinterpret_cast<__half2*>(g_xh);
    __half2* wh2 = reinterpret_cast<__half2*>(g_wh);

    for (long t = tid; t < NX4; t += stride) {
        float4 v = reinterpret_cast<const float4*>(x)[t];
        xh2[2 * t + 0] = __floats2half2_rn(v.x, v.y);
        xh2[2 * t + 1] = __floats2half2_rn(v.z, v.w);
    }
    for (long t = tid; t < NW4; t += stride) {
        float4 v = reinterpret_cast<const float4*>(w)[t];
        wh2[2 * t + 0] = __floats2half2_rn(fsign(v.x), fsign(v.y));
        wh2[2 * t + 1] = __floats2half2_rn(fsign(v.z), fsign(v.w));
    }
    if (tid < N) g_bs[tid] = fsign(b[tid]);
}

// ---------------- GEMM -------------------------------------------------------
// grid (N/BN=32, M/BM=64), 128 threads (4 warps: 2m x 2n), warp tile 64x64.
// 3-stage pipeline, mbarrier full/empty sync, prefetch distance 1.
__global__ void __launch_bounds__(128, 2)
gemm_kernel(float* __restrict__ out) {
    extern __shared__ __half smem[];
    const uint32_t sbase = smem_u32(smem);

    const int tid = threadIdx.x;
    const int wid = tid >> 5;
    const int lane = tid & 31;
    const int warp_m = wid & 1;         // 0..1
    const int warp_n = wid >> 1;        // 0..1

    const int bn = blockIdx.x;          // 0..31
    const int bm = blockIdx.y;          // 0..63

    const __half* gA = g_xh + (size_t)(bm * BM) * K;
    const __half* gB = g_wh + (size_t)(bn * BN) * K;

    auto full_bar  = [&](int s) { return sbase + (uint32_t)s * 16; };
    auto empty_bar = [&](int s) { return sbase + (uint32_t)s * 16 + 8; };

    // ldmatrix per-lane bases
    const int rowA = warp_m * 64 + (lane & 15);
    const int kbA  = (lane >> 4) * 8;                        // halves
    const int rowB = warp_n * 64 + (lane & 7) + (lane >> 4) * 8;
    const int kbB  = ((lane >> 3) & 1) * 8;                  // halves

    float acc[4][8][4];
    #pragma unroll
    for (int i = 0; i < 4; i++)
        #pragma unroll
        for (int j = 0; j < 8; j++)
            #pragma unroll
            for (int e = 0; e < 4; e++) acc[i][j][e] = 0.f;

    auto issue_stage = [&](int kt) {
        const int st = kt % STAGES;
        const uint32_t sA = sbase + SMEM_DATA + st * STAGE_BYTES;
        const uint32_t sB = sA + TILE_BYTES;
        #pragma unroll
        for (int i = 0; i < 8; i++) {
            const int c = tid + i * 128;
            const int row = c >> 3;
            const int kc = c & 7;
            const size_t goff = (size_t)row * K + (size_t)kt * BK + kc * 8;
            cp16(sA + row * ROW_BYTES + kc * 16, gA + goff);
            cp16(sB + row * ROW_BYTES + kc * 16, gB + goff);
        }
        CP_MBAR_ARRIVE(full_bar(st));    // arrive when this thread's cps land
    };

    auto load_frags = [&](int stage, int kk, uint32_t (*a)[4], uint32_t (*b)[4]) {
        const uint32_t sA = sbase + SMEM_DATA + stage * STAGE_BYTES;
        const uint32_t sB = sA + TILE_BYTES;
        #pragma unroll
        for (int im = 0; im < 4; im++)
            ldsm4(a[im], sA + (rowA + im * 16) * ROW_BYTES + (kbA + kk * 16) * 2);
        #pragma unroll
        for (int q = 0; q < 4; q++)
            ldsm4(b[q], sB + (rowB + q * 16) * ROW_BYTES + (kbB + kk * 16) * 2);
    };

    auto mma_half = [&](uint32_t (*a)[4], uint32_t (*b)[4]) {
        #pragma unroll
        for (int im = 0; im < 4; im++)
            #pragma unroll
            for (int jn = 0; jn < 8; jn++)
                mma16816(acc[im][jn],
                         a[im], b[jn >> 1][(jn & 1) * 2],
                                b[jn >> 1][(jn & 1) * 2 + 1]);
    };

    // ---- init barriers: full/empty count = 128 (one arrival per thread) ----
    if (tid == 0) {
        #pragma unroll
        for (int s = 0; s < STAGES; s++) {
            MBAR_INIT(full_bar(s), 128);
            MBAR_INIT(empty_bar(s), 128);
        }
    }
    __syncthreads();

    uint32_t a0[4][4], b0[4][4], a1[4][4], b1[4][4];

    // prologue: stages 0,1 in flight (buffers fresh, no empty wait)
    issue_stage(0);
    issue_stage(1);
    MBAR_WAIT(full_bar(0), 0);           // stage 0 resident (all threads' cps)
    load_frags(0, 0, a0, b0);

    for (int kt = 0; kt < KT; kt++) {
        const int s = kt % STAGES;

        load_frags(s, 1, a1, b1);

        // prefetch stage kt+2 into buffer (kt+2)%3 (last used by stage kt-1);
        // wait for all threads to have finished reading stage kt-1.
        if (kt + 2 < KT) {
            if (kt >= 1)
                MBAR_WAIT(empty_bar((kt + 2) % STAGES), ((kt - 1) / STAGES) & 1);
            issue_stage(kt + 2);
        }
        mma_half(a0, b0);                   // kk=0

        load_frags(s, 2, a0, b0);
        mma_half(a1, b1);                   // kk=1
        load_frags(s, 3, a1, b1);
        MBAR_ARRIVE(empty_bar(s));          // this thread done reading stage kt
        mma_half(a0, b0);                   // kk=2

        if (kt + 1 < KT) {
            MBAR_WAIT(full_bar((kt + 1) % STAGES), ((kt + 1) / STAGES) & 1);
            load_frags((kt + 1) % STAGES, 0, a0, b0);
        }
        mma_half(a1, b1);                   // kk=3
    }

    // ---------------- epilogue: add sign(bias), store fp32 ------------------
    const int col0 = bn * BN + warp_n * 64 + 2 * (lane & 3);
    const int row0 = bm * BM + warp_m * 64 + (lane >> 2);
    #pragma unroll
    for (int jn = 0; jn < 8; jn++) {
        const int c = col0 + jn * 8;
        const float b0v = g_bs[c];
        const float b1v = g_bs[c + 1];
        #pragma unroll
        for (int im = 0; im < 4; im++) {
            const int r = row0 + im * 16;
            float2 v0 = make_float2(acc[im][jn][0] + b0v, acc[im][jn][1] + b1v);
            float2 v1 = make_float2(acc[im][jn][2] + b0v, acc[im][jn][3] + b1v);
            *reinterpret_cast<float2*>(out + (size_t)r * N + c) = v0;
            *reinterpret_cast<float2*>(out + (size_t)(r + 8) * N + c) = v1;
        }
    }
}

// ---------------- host launch ------------------------------------------------
extern "C" void kernel_launch(void* const* d_in, const int* in_sizes, int n_in,
                              void* d_out, int out_size) {
    const float* x = (const float*)d_in[0];
    const float* w = (const float*)d_in[1];
    const float* b = (const float*)d_in[2];
    float* out = (float*)d_out;

    cudaFuncSetAttribute(gemm_kernel, cudaFuncAttributeMaxDynamicSharedMemorySize,
                         SMEM_TOTAL);

    prep_kernel<<<1024, 256>>>(x, w, b);

    dim3 grid(N / BN, M / BM);   // (32, 64)
    gemm_kernel<<<grid, 128, SMEM_TOTAL>>>(out);
}